// round 3
// baseline (speedup 1.0000x reference)
#include <cuda_runtime.h>
#include <cstdint>

#define NMAX 100000
#define EMAX 1700000
#define HID 64
typedef unsigned long long ULL;

// Per-node affine precompute:
// A[n] = x[n] @ W1[0:13] + pos[n] @ W1[13:16] + b1
// B[n] = pos[n] @ W1[13:16]
// edge message hidden: h = relu(A[src] - B[dst]); out = max_dst relu(h @ W2 + b2)
__device__ float g_A[NMAX * HID];
__device__ float g_B[NMAX * HID];
__device__ int   g_cnt[NMAX];     // degree by dst
__device__ int   g_off[NMAX];     // CSR offsets (exclusive prefix of cnt)
__device__ int   g_cur[NMAX];     // scatter cursors
__device__ int   g_srcs[EMAX];    // CSR src ids grouped by dst
__device__ int   g_bsum[128];     // scan block sums
__device__ int   g_is32;          // 1 if edge_index is int32, 0 if int64

// ---------------- edge dtype detection ----------------
// int64 little-endian values < 2^31 have all odd int32 words == 0.
__global__ void detect_kernel(const int* __restrict__ e, long long n_words) {
    __shared__ int any;
    if (threadIdx.x == 0) any = 0;
    __syncthreads();
    long long lim = n_words < 4096 ? n_words : 4096;
    for (long long i = 1 + 2 * (long long)threadIdx.x; i < lim; i += 2 * blockDim.x)
        if (e[i] != 0) any = 1;
    __syncthreads();
    if (threadIdx.x == 0) g_is32 = any;
}

__device__ __forceinline__ int load_idx(const void* e, long long E,
                                        long long i, int which, int is32) {
    if (is32) return ((const int*)e)[which * E + i];
    return (int)((const long long*)e)[which * E + i];
}

// ---------------- per-node precompute ----------------
__global__ __launch_bounds__(256) void precompute_kernel(
    const float* __restrict__ x, const float* __restrict__ pos,
    const float* __restrict__ W1, const float* __restrict__ b1,
    int n_nodes)
{
    __shared__ float m[16][16];
    __shared__ float W1s[16 * 64];
    __shared__ float b1s[64];
    int tid = threadIdx.x;
    int node0 = blockIdx.x * 16;
    {
        int nl = tid >> 4, f = tid & 15;
        int node = node0 + nl;
        float v = 0.0f;
        if (node < n_nodes)
            v = (f < 13) ? x[node * 13 + f] : pos[node * 3 + (f - 13)];
        m[nl][f] = v;
    }
    #pragma unroll
    for (int j = 0; j < 4; j++) W1s[tid + j * 256] = W1[tid + j * 256];
    if (tid < 64) b1s[tid] = b1[tid];
    __syncthreads();

    int col = tid & 63;
    #pragma unroll
    for (int r = 0; r < 4; r++) {
        int nloc = r * 4 + (tid >> 6);
        int node = node0 + nloc;
        if (node >= n_nodes) continue;
        float accA = b1s[col];
        float accB = 0.0f;
        #pragma unroll
        for (int i = 0; i < 13; i++)
            accA = fmaf(m[nloc][i], W1s[i * 64 + col], accA);
        #pragma unroll
        for (int p = 0; p < 3; p++) {
            float wv = W1s[(13 + p) * 64 + col];
            float pv = m[nloc][13 + p];
            accA = fmaf(pv, wv, accA);
            accB = fmaf(pv, wv, accB);
        }
        g_A[node * 64 + col] = accA;
        g_B[node * 64 + col] = accB;
    }
}

// ---------------- CSR build ----------------
__global__ void zero_cnt_kernel(int n) {
    int i = blockIdx.x * blockDim.x + threadIdx.x;
    if (i < n) g_cnt[i] = 0;
}

__global__ void hist_kernel(const void* __restrict__ e, long long E) {
    long long i = (long long)blockIdx.x * blockDim.x + threadIdx.x;
    if (i < E) {
        int d = load_idx(e, E, i, 1, g_is32);
        atomicAdd(&g_cnt[d], 1);
    }
}

// scan level 1: 1024-wide block scans; g_off gets block-local exclusive prefix
__global__ __launch_bounds__(1024) void scan1_kernel(int n) {
    __shared__ int sm[1024];
    int t = threadIdx.x;
    int idx = blockIdx.x * 1024 + t;
    int v = (idx < n) ? g_cnt[idx] : 0;
    sm[t] = v;
    __syncthreads();
    #pragma unroll
    for (int d = 1; d < 1024; d <<= 1) {
        int u = (t >= d) ? sm[t - d] : 0;
        __syncthreads();
        if (t >= d) sm[t] += u;
        __syncthreads();
    }
    if (idx < n) g_off[idx] = sm[t] - v;          // exclusive
    if (t == 1023) g_bsum[blockIdx.x] = sm[t];    // block total
}

// scan level 2: exclusive scan of <=1024 block sums, in place
__global__ __launch_bounds__(1024) void scan2_kernel(int nb) {
    __shared__ int sm[1024];
    int t = threadIdx.x;
    int v = (t < nb) ? g_bsum[t] : 0;
    sm[t] = v;
    __syncthreads();
    #pragma unroll
    for (int d = 1; d < 1024; d <<= 1) {
        int u = (t >= d) ? sm[t - d] : 0;
        __syncthreads();
        if (t >= d) sm[t] += u;
        __syncthreads();
    }
    if (t < nb) g_bsum[t] = sm[t] - v;            // exclusive
}

// scan level 3: add block offsets; copy to cursor
__global__ void scan3_kernel(int n) {
    int i = blockIdx.x * blockDim.x + threadIdx.x;
    if (i < n) {
        int o = g_off[i] + g_bsum[i >> 10];
        g_off[i] = o;
        g_cur[i] = o;
    }
}

__global__ void scatter_kernel(const void* __restrict__ e, long long E) {
    long long i = (long long)blockIdx.x * blockDim.x + threadIdx.x;
    if (i < E) {
        int is32 = g_is32;
        int s = load_idx(e, E, i, 0, is32);
        int d = load_idx(e, E, i, 1, is32);
        int p = atomicAdd(&g_cur[d], 1);
        if (p < EMAX) g_srcs[p] = s;
    }
}

// ---------------- aggregation: one warp per dst node ----------------
// Packed dual-fp32 FMA (sm_100+)
__device__ __forceinline__ void fma2(ULL& d, ULL a, ULL b) {
    asm("fma.rn.f32x2 %0, %1, %2, %0;" : "+l"(d) : "l"(a), "l"(b));
}
__device__ __forceinline__ float lo32(ULL a) { return __uint_as_float((unsigned)a); }
__device__ __forceinline__ float hi32(ULL a) { return __uint_as_float((unsigned)(a >> 32)); }

__global__ __launch_bounds__(256) void agg_kernel(
    const float* __restrict__ W2, const float* __restrict__ b2,
    float* __restrict__ out, int n_nodes)
{
    // W2t[col][k], row padded to 68 floats: LDS.128 phases tile all 32 banks.
    __shared__ __align__(16) float W2t[64 * 68];
    __shared__ __align__(16) float tsm[8][8 * 64];  // [warp][edge][k]
    int tid = threadIdx.x;
    for (int i = tid; i < 4096; i += 256) {
        int k = i >> 6, c = i & 63;
        W2t[c * 68 + k] = W2[i];
    }
    __syncthreads();

    int lane = tid & 31;
    int w = tid >> 5;
    int node = blockIdx.x * 8 + w;
    if (node >= n_nodes) return;   // after the only __syncthreads

    float* ts = tsm[w];
    int s0  = g_off[node];
    int deg = g_cnt[node];
    float2 bv = *(const float2*)&g_B[node * 64 + 2 * lane];  // k = 2l, 2l+1
    float bc0 = b2[lane], bc1 = b2[lane + 32];
    float best0 = 0.0f, best1 = 0.0f;   // relu floor + empty-segment value

    int nfull = deg >> 3;
    const ULL* wp0 = (const ULL*)&W2t[lane * 68];
    const ULL* wp1 = (const ULL*)&W2t[(lane + 32) * 68];

    for (int b = 0; b < nfull; b++) {
        int base = s0 + (b << 3);
        int sid = (lane < 8) ? g_srcs[base + lane] : 0;
        #pragma unroll
        for (int e = 0; e < 8; e++) {
            int s = __shfl_sync(0xffffffffu, sid, e);
            float2 av = *(const float2*)&g_A[s * 64 + 2 * lane];
            float t0 = fmaxf(av.x - bv.x, 0.0f);
            float t1 = fmaxf(av.y - bv.y, 0.0f);
            *(float2*)&ts[e * 64 + 2 * lane] = make_float2(t0, t1);
        }
        __syncwarp();

        ULL acc[8][2];
        #pragma unroll
        for (int e = 0; e < 8; e++) { acc[e][0] = 0ull; acc[e][1] = 0ull; }

        #pragma unroll
        for (int k4 = 0; k4 < 16; k4++) {
            ULL w00 = wp0[2 * k4], w01 = wp0[2 * k4 + 1];
            ULL w10 = wp1[2 * k4], w11 = wp1[2 * k4 + 1];
            #pragma unroll
            for (int e = 0; e < 8; e++) {
                const ULL* t2 = (const ULL*)&ts[e * 64 + 4 * k4];
                ULL ta = t2[0], tb = t2[1];
                fma2(acc[e][0], ta, w00); fma2(acc[e][0], tb, w01);
                fma2(acc[e][1], ta, w10); fma2(acc[e][1], tb, w11);
            }
        }
        #pragma unroll
        for (int e = 0; e < 8; e++) {
            float v0 = lo32(acc[e][0]) + hi32(acc[e][0]) + bc0;
            float v1 = lo32(acc[e][1]) + hi32(acc[e][1]) + bc1;
            best0 = fmaxf(best0, v0);
            best1 = fmaxf(best1, v1);
        }
        __syncwarp();
    }

    // tail (deg & 7 edges)
    int rem = deg & 7;
    if (rem) {
        int base = s0 + (nfull << 3);
        int sid = (lane < rem) ? g_srcs[base + lane] : 0;
        for (int e = 0; e < rem; e++) {
            int s = __shfl_sync(0xffffffffu, sid, e);
            float2 av = *(const float2*)&g_A[s * 64 + 2 * lane];
            float t0 = fmaxf(av.x - bv.x, 0.0f);
            float t1 = fmaxf(av.y - bv.y, 0.0f);
            *(float2*)&ts[2 * lane]      = make_float2(t0, t1);
            __syncwarp();
            ULL a0 = 0ull, a1 = 0ull;
            #pragma unroll
            for (int k4 = 0; k4 < 16; k4++) {
                const ULL* t2 = (const ULL*)&ts[4 * k4];
                ULL ta = t2[0], tb = t2[1];
                fma2(a0, ta, wp0[2 * k4]); fma2(a0, tb, wp0[2 * k4 + 1]);
                fma2(a1, ta, wp1[2 * k4]); fma2(a1, tb, wp1[2 * k4 + 1]);
            }
            float v0 = lo32(a0) + hi32(a0) + bc0;
            float v1 = lo32(a1) + hi32(a1) + bc1;
            best0 = fmaxf(best0, v0);
            best1 = fmaxf(best1, v1);
            __syncwarp();
        }
    }

    out[node * 64 + lane]      = best0;
    out[node * 64 + 32 + lane] = best1;
}

extern "C" void kernel_launch(void* const* d_in, const int* in_sizes, int n_in,
                              void* d_out, int out_size) {
    const float* x   = (const float*)d_in[0];
    const float* pos = (const float*)d_in[1];
    const float* W1  = (const float*)d_in[2];
    const float* b1  = (const float*)d_in[3];
    const float* W2  = (const float*)d_in[4];
    const float* b2  = (const float*)d_in[5];
    const void*  eidx = d_in[6];

    int n_nodes = in_sizes[0] / 13;
    if (n_nodes > NMAX) n_nodes = NMAX;
    long long E = (long long)in_sizes[6] / 2;
    float* out = (float*)d_out;

    int nb_nodes = (n_nodes + 255) / 256;
    int nb_edges = (int)((E + 255) / 256);
    int nb_scan  = (n_nodes + 1023) / 1024;

    detect_kernel<<<1, 256>>>((const int*)eidx, 2 * E);
    precompute_kernel<<<(n_nodes + 15) / 16, 256>>>(x, pos, W1, b1, n_nodes);
    zero_cnt_kernel<<<nb_nodes, 256>>>(n_nodes);
    hist_kernel<<<nb_edges, 256>>>(eidx, E);
    scan1_kernel<<<nb_scan, 1024>>>(n_nodes);
    scan2_kernel<<<1, 1024>>>(nb_scan);
    scan3_kernel<<<nb_nodes, 256>>>(n_nodes);
    scatter_kernel<<<nb_edges, 256>>>(eidx, E);
    agg_kernel<<<(n_nodes + 7) / 8, 256>>>(W2, b2, out, n_nodes);
}

// round 4
// speedup vs baseline: 1.1525x; 1.1525x over previous
#include <cuda_runtime.h>
#include <cstdint>

#define NMAX 100000
#define EMAX 1700000
#define HID 64
typedef unsigned long long ULL;

// Per-node affine precompute:
// A[n] = x[n] @ W1[0:13] + pos[n] @ W1[13:16] + b1
// B[n] = pos[n] @ W1[13:16]
// edge message hidden: h = relu(A[src] - B[dst]); out = max_dst relu(h @ W2 + b2)
__device__ float g_A[NMAX * HID];
__device__ float g_B[NMAX * HID];
__device__ int   g_cnt[NMAX];     // degree by dst
__device__ int   g_off[NMAX];     // CSR offsets (exclusive prefix of cnt)
__device__ int   g_cur[NMAX];     // scatter cursors
__device__ int   g_srcs[EMAX];    // CSR src ids grouped by dst
__device__ int   g_bsum[128];     // scan block sums
__device__ int   g_is32;          // 1 if edge_index is int32, 0 if int64

// ---------------- edge dtype detection ----------------
// int64 little-endian values < 2^31 have all odd int32 words == 0.
__global__ void detect_kernel(const int* __restrict__ e, long long n_words) {
    __shared__ int any;
    if (threadIdx.x == 0) any = 0;
    __syncthreads();
    long long lim = n_words < 4096 ? n_words : 4096;
    for (long long i = 1 + 2 * (long long)threadIdx.x; i < lim; i += 2 * blockDim.x)
        if (e[i] != 0) any = 1;
    __syncthreads();
    if (threadIdx.x == 0) g_is32 = any;
}

__device__ __forceinline__ int load_idx(const void* e, long long E,
                                        long long i, int which, int is32) {
    if (is32) return ((const int*)e)[which * E + i];
    return (int)((const long long*)e)[which * E + i];
}

// ---------------- per-node precompute ----------------
__global__ __launch_bounds__(256) void precompute_kernel(
    const float* __restrict__ x, const float* __restrict__ pos,
    const float* __restrict__ W1, const float* __restrict__ b1,
    int n_nodes)
{
    __shared__ float m[16][16];
    __shared__ float W1s[16 * 64];
    __shared__ float b1s[64];
    int tid = threadIdx.x;
    int node0 = blockIdx.x * 16;
    {
        int nl = tid >> 4, f = tid & 15;
        int node = node0 + nl;
        float v = 0.0f;
        if (node < n_nodes)
            v = (f < 13) ? x[node * 13 + f] : pos[node * 3 + (f - 13)];
        m[nl][f] = v;
    }
    #pragma unroll
    for (int j = 0; j < 4; j++) W1s[tid + j * 256] = W1[tid + j * 256];
    if (tid < 64) b1s[tid] = b1[tid];
    __syncthreads();

    int col = tid & 63;
    #pragma unroll
    for (int r = 0; r < 4; r++) {
        int nloc = r * 4 + (tid >> 6);
        int node = node0 + nloc;
        if (node >= n_nodes) continue;
        float accA = b1s[col];
        float accB = 0.0f;
        #pragma unroll
        for (int i = 0; i < 13; i++)
            accA = fmaf(m[nloc][i], W1s[i * 64 + col], accA);
        #pragma unroll
        for (int p = 0; p < 3; p++) {
            float wv = W1s[(13 + p) * 64 + col];
            float pv = m[nloc][13 + p];
            accA = fmaf(pv, wv, accA);
            accB = fmaf(pv, wv, accB);
        }
        g_A[node * 64 + col] = accA;
        g_B[node * 64 + col] = accB;
    }
}

// ---------------- CSR build ----------------
__global__ void zero_cnt_kernel(int n) {
    int i = blockIdx.x * blockDim.x + threadIdx.x;
    if (i < n) g_cnt[i] = 0;
}

__global__ void hist_kernel(const void* __restrict__ e, long long E) {
    long long i = (long long)blockIdx.x * blockDim.x + threadIdx.x;
    if (i < E) {
        int d = load_idx(e, E, i, 1, g_is32);
        atomicAdd(&g_cnt[d], 1);
    }
}

// scan level 1: 1024-wide block scans; g_off gets block-local exclusive prefix
__global__ __launch_bounds__(1024) void scan1_kernel(int n) {
    __shared__ int sm[1024];
    int t = threadIdx.x;
    int idx = blockIdx.x * 1024 + t;
    int v = (idx < n) ? g_cnt[idx] : 0;
    sm[t] = v;
    __syncthreads();
    #pragma unroll
    for (int d = 1; d < 1024; d <<= 1) {
        int u = (t >= d) ? sm[t - d] : 0;
        __syncthreads();
        if (t >= d) sm[t] += u;
        __syncthreads();
    }
    if (idx < n) g_off[idx] = sm[t] - v;          // exclusive
    if (t == 1023) g_bsum[blockIdx.x] = sm[t];    // block total
}

// scan level 2: exclusive scan of <=1024 block sums, in place
__global__ __launch_bounds__(1024) void scan2_kernel(int nb) {
    __shared__ int sm[1024];
    int t = threadIdx.x;
    int v = (t < nb) ? g_bsum[t] : 0;
    sm[t] = v;
    __syncthreads();
    #pragma unroll
    for (int d = 1; d < 1024; d <<= 1) {
        int u = (t >= d) ? sm[t - d] : 0;
        __syncthreads();
        if (t >= d) sm[t] += u;
        __syncthreads();
    }
    if (t < nb) g_bsum[t] = sm[t] - v;            // exclusive
}

// scan level 3: add block offsets; copy to cursor
__global__ void scan3_kernel(int n) {
    int i = blockIdx.x * blockDim.x + threadIdx.x;
    if (i < n) {
        int o = g_off[i] + g_bsum[i >> 10];
        g_off[i] = o;
        g_cur[i] = o;
    }
}

__global__ void scatter_kernel(const void* __restrict__ e, long long E) {
    long long i = (long long)blockIdx.x * blockDim.x + threadIdx.x;
    if (i < E) {
        int is32 = g_is32;
        int s = load_idx(e, E, i, 0, is32);
        int d = load_idx(e, E, i, 1, is32);
        int p = atomicAdd(&g_cur[d], 1);
        if (p < EMAX) g_srcs[p] = s;
    }
}

// ---------------- aggregation: persistent blocks, one warp per node ----------------
// Packed dual-fp32 FMA (sm_100+)
__device__ __forceinline__ void fma2(ULL& d, ULL a, ULL b) {
    asm("fma.rn.f32x2 %0, %1, %2, %0;" : "+l"(d) : "l"(a), "l"(b));
}
__device__ __forceinline__ float lo32(ULL a) { return __uint_as_float((unsigned)a); }
__device__ __forceinline__ float hi32(ULL a) { return __uint_as_float((unsigned)(a >> 32)); }

#define AGG_BLOCKS 444

__global__ __launch_bounds__(256) void agg_kernel(
    const float* __restrict__ W2, const float* __restrict__ b2,
    float* __restrict__ out, int n_nodes)
{
    // W2t[col][k], row padded to 68 floats: LDS.128 phases tile all 32 banks.
    __shared__ __align__(16) float W2t[64 * 68];
    __shared__ __align__(16) float tsm[8][8 * 64];  // [warp][edge][k]
    int tid = threadIdx.x;
    for (int i = tid; i < 4096; i += 256) {
        int k = i >> 6, c = i & 63;
        W2t[c * 68 + k] = W2[i];
    }
    __syncthreads();

    int lane = tid & 31;
    int w = tid >> 5;
    float* ts = tsm[w];
    float bc0 = b2[lane], bc1 = b2[lane + 32];
    const ULL* wp0 = (const ULL*)&W2t[lane * 68];
    const ULL* wp1 = (const ULL*)&W2t[(lane + 32) * 68];

    int gwarp  = blockIdx.x * 8 + w;
    int nwarps = AGG_BLOCKS * 8;

    for (int node = gwarp; node < n_nodes; node += nwarps) {
        int s0  = g_off[node];
        int deg = g_cnt[node];
        float2 bv = *(const float2*)&g_B[node * 64 + 2 * lane];  // k = 2l, 2l+1
        float best0 = 0.0f, best1 = 0.0f;   // relu floor == empty-segment value

        int nblk = (deg + 7) >> 3;
        for (int b = 0; b < nblk; b++) {
            int base = s0 + (b << 3);
            int cnt = deg - (b << 3);
            if (cnt > 8) cnt = 8;
            int sid = (lane < cnt) ? g_srcs[base + lane] : -1;

            #pragma unroll
            for (int e = 0; e < 8; e++) {
                int s = __shfl_sync(0xffffffffu, sid, e);
                float t0 = 0.0f, t1 = 0.0f;
                if (s >= 0) {
                    float2 av = *(const float2*)&g_A[s * 64 + 2 * lane];
                    t0 = fmaxf(av.x - bv.x, 0.0f);
                    t1 = fmaxf(av.y - bv.y, 0.0f);
                }
                *(float2*)&ts[e * 64 + 2 * lane] = make_float2(t0, t1);
            }
            __syncwarp();

            ULL acc[8][2];
            #pragma unroll
            for (int e = 0; e < 8; e++) { acc[e][0] = 0ull; acc[e][1] = 0ull; }

            #pragma unroll
            for (int k4 = 0; k4 < 16; k4++) {
                ULL w00 = wp0[2 * k4], w01 = wp0[2 * k4 + 1];
                ULL w10 = wp1[2 * k4], w11 = wp1[2 * k4 + 1];
                #pragma unroll
                for (int e = 0; e < 8; e++) {
                    const ULL* t2 = (const ULL*)&ts[e * 64 + 4 * k4];
                    ULL ta = t2[0], tb = t2[1];
                    fma2(acc[e][0], ta, w00); fma2(acc[e][0], tb, w01);
                    fma2(acc[e][1], ta, w10); fma2(acc[e][1], tb, w11);
                }
            }
            #pragma unroll
            for (int e = 0; e < 8; e++) {
                if (e < cnt) {
                    float v0 = lo32(acc[e][0]) + hi32(acc[e][0]) + bc0;
                    float v1 = lo32(acc[e][1]) + hi32(acc[e][1]) + bc1;
                    best0 = fmaxf(best0, v0);
                    best1 = fmaxf(best1, v1);
                }
            }
            __syncwarp();   // ts reused next block
        }

        out[node * 64 + lane]      = best0;
        out[node * 64 + 32 + lane] = best1;
    }
}

extern "C" void kernel_launch(void* const* d_in, const int* in_sizes, int n_in,
                              void* d_out, int out_size) {
    const float* x   = (const float*)d_in[0];
    const float* pos = (const float*)d_in[1];
    const float* W1  = (const float*)d_in[2];
    const float* b1  = (const float*)d_in[3];
    const float* W2  = (const float*)d_in[4];
    const float* b2  = (const float*)d_in[5];
    const void*  eidx = d_in[6];

    int n_nodes = in_sizes[0] / 13;
    if (n_nodes > NMAX) n_nodes = NMAX;
    long long E = (long long)in_sizes[6] / 2;
    float* out = (float*)d_out;

    int nb_nodes = (n_nodes + 255) / 256;
    int nb_edges = (int)((E + 255) / 256);
    int nb_scan  = (n_nodes + 1023) / 1024;

    detect_kernel<<<1, 256>>>((const int*)eidx, 2 * E);
    precompute_kernel<<<(n_nodes + 15) / 16, 256>>>(x, pos, W1, b1, n_nodes);
    zero_cnt_kernel<<<nb_nodes, 256>>>(n_nodes);
    hist_kernel<<<nb_edges, 256>>>(eidx, E);
    scan1_kernel<<<nb_scan, 1024>>>(n_nodes);
    scan2_kernel<<<1, 1024>>>(nb_scan);
    scan3_kernel<<<nb_nodes, 256>>>(n_nodes);
    scatter_kernel<<<nb_edges, 256>>>(eidx, E);
    agg_kernel<<<AGG_BLOCKS, 256>>>(W2, b2, out, n_nodes);
}